// round 11
// baseline (speedup 1.0000x reference)
#include <cuda_runtime.h>
#include <math.h>
#include <stdint.h>

#define NN 50000
#define NE 640000
#define DIN 128
#define DH1 128
#define DH2 256
#define NT1 (3 * DH1)   // 384
#define NT2 (3 * DH2)   // 768

// ---------------- device scratch ----------------
__device__ unsigned g_xt[NN * DIN];     // x pre-converted to tf32 bits
__device__ float    g_c1[NN * NT1];     // [xl1 | xr1 | res1] per node (fp32)
__device__ float    g_h1[NN * DH1];     // holds tf32 BITS (written by edge layer 1)
__device__ float    g_c2[NN * NT2];     // [xl2 | xr2 | res2] per node (fp32)
__device__ unsigned g_W1[DIN * NT1];    // [k][3F], tf32 bits
__device__ unsigned g_W2[DH1 * NT2];
__device__ float    g_b1p[NT1];
__device__ float    g_b2p[NT2];
__device__ int      g_rowptr[NN + 1];
__device__ int      g_hist[NN];
__device__ int      g_cursor[NN];
__device__ int      g_srcs[NE];
__device__ int      g_is64;
#define SCAN_NB 98
__device__ int      g_bsum[SCAN_NB];
__device__ int      g_boff[SCAN_NB];

__device__ __forceinline__ unsigned f2tf32(float f) {
    unsigned u;
    asm("cvt.rna.tf32.f32 %0, %1;" : "=r"(u) : "f"(f));
    return u;
}
__device__ __forceinline__ void cp_async16(uint32_t dst, const void* src) {
    asm volatile("cp.async.cg.shared.global [%0], [%1], 16;" :: "r"(dst), "l"(src));
}
#define CP_COMMIT() asm volatile("cp.async.commit_group;" ::: "memory")
#define CP_WAIT0()  asm volatile("cp.async.wait_group 0;" ::: "memory")
#define CP_WAIT1()  asm volatile("cp.async.wait_group 1;" ::: "memory")

// ---------------- edge_index dtype detection ----------------
__global__ void detect_kernel(const unsigned int* __restrict__ w) {
    __shared__ int any_nonzero;
    if (threadIdx.x == 0) any_nonzero = 0;
    __syncthreads();
    unsigned int v = w[2 * threadIdx.x + 1];
    if (v != 0u) atomicOr(&any_nonzero, 1);
    __syncthreads();
    if (threadIdx.x == 0) g_is64 = any_nonzero ? 0 : 1;
}
__device__ __forceinline__ int load_idx(const void* ei, int i) {
    return g_is64 ? (int)((const long long*)ei)[i] : ((const int*)ei)[i];
}

// ---------------- x -> tf32 bits ----------------
__global__ void xconv_kernel(const float* __restrict__ x) {
    int i = blockIdx.x * blockDim.x + threadIdx.x;  // float4 index
    if (i < NN * DIN / 4) {
        float4 v = ((const float4*)x)[i];
        uint4 u;
        u.x = f2tf32(v.x); u.y = f2tf32(v.y); u.z = f2tf32(v.z); u.w = f2tf32(v.w);
        ((uint4*)g_xt)[i] = u;
    }
}

// ---------------- weight packing: Wp[k][3F] = tf32([Wl|Wr|Wres]), bias padded ------
__global__ void pack_all_kernel(
    const float* __restrict__ Wl1, const float* __restrict__ Wr1,
    const float* __restrict__ Wres1, const float* __restrict__ b1,
    const float* __restrict__ Wl2, const float* __restrict__ Wr2,
    const float* __restrict__ Wres2, const float* __restrict__ b2)
{
    int idx = blockIdx.x * blockDim.x + threadIdx.x;
    const int S1 = DIN * NT1;
    const int S2 = DH1 * NT2;
    if (idx < S1) {
        int k = idx / NT1, c = idx % NT1;
        float v = (c < DH1) ? Wl1[k * DH1 + c]
                : (c < 2 * DH1) ? Wr1[k * DH1 + (c - DH1)]
                : Wres1[k * DH1 + (c - 2 * DH1)];
        g_W1[idx] = f2tf32(v);
    } else if (idx < S1 + S2) {
        int j = idx - S1;
        int k = j / NT2, c = j % NT2;
        float v = (c < DH2) ? Wl2[k * DH2 + c]
                : (c < 2 * DH2) ? Wr2[k * DH2 + (c - DH2)]
                : Wres2[k * DH2 + (c - 2 * DH2)];
        g_W2[j] = f2tf32(v);
    }
    if (idx < NT1) g_b1p[idx] = (idx < 2 * DH1) ? 0.f : b1[idx - 2 * DH1];
    if (idx < NT2) g_b2p[idx] = (idx < 2 * DH2) ? 0.f : b2[idx - 2 * DH2];
}

// ---------------- CSR build ----------------
__global__ void hist_kernel(const void* __restrict__ ei) {
    int e = blockIdx.x * blockDim.x + threadIdx.x;
    if (e < NE) atomicAdd(&g_hist[load_idx(ei, NE + e)], 1);
}
__global__ void scan_pass1() {
    __shared__ int sh[512];
    int t = threadIdx.x;
    int i = blockIdx.x * 512 + t;
    int v = (i < NN) ? g_hist[i] : 0;
    sh[t] = v;
    __syncthreads();
    for (int off = 1; off < 512; off <<= 1) {
        int u = (t >= off) ? sh[t - off] : 0;
        __syncthreads();
        sh[t] += u;
        __syncthreads();
    }
    if (i < NN) g_rowptr[i] = sh[t] - v;
    if (t == 511) g_bsum[blockIdx.x] = sh[511];
}
__global__ void scan_pass2() {
    __shared__ int sh[128];
    int t = threadIdx.x;
    int v = (t < SCAN_NB) ? g_bsum[t] : 0;
    sh[t] = v;
    __syncthreads();
    for (int off = 1; off < 128; off <<= 1) {
        int u = (t >= off) ? sh[t - off] : 0;
        __syncthreads();
        sh[t] += u;
        __syncthreads();
    }
    if (t < SCAN_NB) g_boff[t] = sh[t] - v;
    if (t == 0) g_rowptr[NN] = NE;
}
__global__ void scan_pass3() {
    int i = blockIdx.x * 512 + threadIdx.x;
    if (i < NN) {
        int r = g_rowptr[i] + g_boff[blockIdx.x];
        g_rowptr[i] = r;
        g_cursor[i] = r;
    }
}
__global__ void scatter_kernel(const void* __restrict__ ei) {
    int e = blockIdx.x * blockDim.x + threadIdx.x;
    if (e < NE) {
        int d = load_idx(ei, NE + e);
        int p = atomicAdd(&g_cursor[d], 1);
        g_srcs[p] = load_idx(ei, e);
    }
}

// ---------------- tf32 mma.sync GEMM: BM=128 BN=128 BK=16, 3-stage cp.async pipe ----
#define AS_RS 20
#define BS_RS 140
#define NSTAGE 3

__global__ void __launch_bounds__(128) gemm_tf32_kernel(
    const unsigned* __restrict__ A, const unsigned* __restrict__ W,
    const float* __restrict__ bias, float* __restrict__ C,
    int M, int K, int N)
{
    __shared__ unsigned As[NSTAGE][128 * AS_RS];
    __shared__ unsigned Bs[NSTAGE][16 * BS_RS];

    int tid = threadIdx.x;
    int bm = blockIdx.y * 128;
    int bn = blockIdx.x * 128;

    int warpId = tid >> 5;
    int lane = tid & 31;
    int gid = lane >> 2;      // 0..7
    int tig = lane & 3;       // 0..3
    int warp_m = warpId >> 1; // 0..1
    int warp_n = warpId & 1;  // 0..1

    float acc[4][8][4];
#pragma unroll
    for (int mt = 0; mt < 4; mt++)
#pragma unroll
        for (int nt = 0; nt < 8; nt++)
#pragma unroll
            for (int r = 0; r < 4; r++) acc[mt][nt][r] = 0.f;

    // A staging: thread = row (0..127); OOB rows clamp to M-1 (read-safe, discarded)
    int arow = bm + tid; if (arow >= M) arow = M - 1;
    const unsigned* a_ptr = A + (size_t)arow * K;
    // B staging: b_row = tid&15, colgroup = tid>>4 (8 groups x 16 cols)
    int b_row = tid & 15;
    int b_colg = (tid >> 4) * 16;
    const unsigned* w_ptr = W + (size_t)b_row * N + bn + b_colg;
    uint32_t as_base[NSTAGE], bs_base[NSTAGE];
#pragma unroll
    for (int s = 0; s < NSTAGE; s++) {
        as_base[s] = (uint32_t)__cvta_generic_to_shared(&As[s][tid * AS_RS]);
        bs_base[s] = (uint32_t)__cvta_generic_to_shared(&Bs[s][b_row * BS_RS + b_colg]);
    }

    const int KT = K >> 4;

    // prologue: issue copies for tiles 0 and 1 (two commit groups in flight)
#pragma unroll
    for (int st = 0; st < 2; st++) {
#pragma unroll
        for (int j = 0; j < 4; j++) {
            cp_async16(as_base[st] + j * 16, a_ptr + st * 16 + j * 4);
            cp_async16(bs_base[st] + j * 16, w_ptr + (size_t)st * 16 * N + j * 4);
        }
        CP_COMMIT();
    }

    for (int kt = 0; kt < KT; kt++) {
        int buf = kt % NSTAGE;

        // wait for tile kt's copy; keep one further group in flight in steady state
        if (kt + 1 < KT) CP_WAIT1(); else CP_WAIT0();
        __syncthreads();

        // issue copy for tile kt+2 into buf (kt+2)%NSTAGE (safe: that buffer's MMAs
        // finished before the sync above)
        if (kt + 2 < KT) {
            int nb = (kt + 2) % NSTAGE;
#pragma unroll
            for (int j = 0; j < 4; j++) {
                cp_async16(as_base[nb] + j * 16, a_ptr + (kt + 2) * 16 + j * 4);
                cp_async16(bs_base[nb] + j * 16, w_ptr + (size_t)(kt + 2) * 16 * N + j * 4);
            }
            CP_COMMIT();
        }

        const unsigned* Ac = As[buf];
        const unsigned* Bc = Bs[buf];
#pragma unroll
        for (int s = 0; s < 2; s++) {
            int kb = s * 8;
            unsigned afr[4][4];
#pragma unroll
            for (int mt = 0; mt < 4; mt++) {
                int rm = warp_m * 64 + mt * 16 + gid;
                afr[mt][0] = Ac[(rm + 0) * AS_RS + kb + tig];
                afr[mt][1] = Ac[(rm + 8) * AS_RS + kb + tig];
                afr[mt][2] = Ac[(rm + 0) * AS_RS + kb + tig + 4];
                afr[mt][3] = Ac[(rm + 8) * AS_RS + kb + tig + 4];
            }
#pragma unroll
            for (int nt = 0; nt < 8; nt++) {
                int cn = warp_n * 64 + nt * 8 + gid;
                unsigned b0 = Bc[(kb + tig) * BS_RS + cn];
                unsigned b1 = Bc[(kb + tig + 4) * BS_RS + cn];
#pragma unroll
                for (int mt = 0; mt < 4; mt++) {
                    asm volatile(
                        "mma.sync.aligned.m16n8k8.row.col.f32.tf32.tf32.f32 "
                        "{%0,%1,%2,%3}, {%4,%5,%6,%7}, {%8,%9}, {%0,%1,%2,%3};"
                        : "+f"(acc[mt][nt][0]), "+f"(acc[mt][nt][1]),
                          "+f"(acc[mt][nt][2]), "+f"(acc[mt][nt][3])
                        : "r"(afr[mt][0]), "r"(afr[mt][1]),
                          "r"(afr[mt][2]), "r"(afr[mt][3]),
                          "r"(b0), "r"(b1));
                }
            }
        }
        __syncthreads();
    }

    // epilogue (bias pre-padded with zeros for xl/xr columns)
#pragma unroll
    for (int mt = 0; mt < 4; mt++) {
        int r0 = bm + warp_m * 64 + mt * 16 + gid;
        int r1 = r0 + 8;
#pragma unroll
        for (int nt = 0; nt < 8; nt++) {
            int col = bn + warp_n * 64 + nt * 8 + tig * 2;
            float bx = bias[col], by = bias[col + 1];
            if (r0 < M) {
                float2 o = make_float2(acc[mt][nt][0] + bx, acc[mt][nt][1] + by);
                *(float2*)&C[(size_t)r0 * N + col] = o;
            }
            if (r1 < M) {
                float2 o = make_float2(acc[mt][nt][2] + bx, acc[mt][nt][3] + by);
                *(float2*)&C[(size_t)r1 * N + col] = o;
            }
        }
    }
}

// ---------------- fused edge pass: warp-per-dst, chunked online softmax ----------------
// write_tf32: layer-1 output is consumed only by GEMM2 -> store tf32 bits directly.
template <int F>
__global__ void __launch_bounds__(256) edge_kernel(
    const float* __restrict__ C, const float* __restrict__ att,
    float* __restrict__ out, int apply_elu, int write_tf32)
{
    constexpr int NT = 3 * F;
    constexpr int V = F / 32;
    constexpr int EC = 4;
    int warp = (blockIdx.x * blockDim.x + threadIdx.x) >> 5;
    int lane = threadIdx.x & 31;
    if (warp >= NN) return;
    int dst = warp;
    const int base = lane * V;

    float a[V], xrv[V], acc[V];
#pragma unroll
    for (int j = 0; j < V; j += 4) {
        float4 t = *(const float4*)&att[base + j];
        a[j] = t.x; a[j + 1] = t.y; a[j + 2] = t.z; a[j + 3] = t.w;
        float4 r = *(const float4*)&C[(size_t)dst * NT + F + base + j];
        xrv[j] = r.x; xrv[j + 1] = r.y; xrv[j + 2] = r.z; xrv[j + 3] = r.w;
    }
#pragma unroll
    for (int j = 0; j < V; j++) acc[j] = 0.f;

    float emax = -INFINITY, denom = 0.f;
    int p0 = g_rowptr[dst], p1 = g_rowptr[dst + 1];

    for (int p = p0; p < p1; p += EC) {
        int sidx[EC];
        float xlv[EC][V];
#pragma unroll
        for (int c = 0; c < EC; c++)
            sidx[c] = (p + c < p1) ? g_srcs[p + c] : -1;
#pragma unroll
        for (int c = 0; c < EC; c++) {
            if (sidx[c] >= 0) {
#pragma unroll
                for (int j = 0; j < V; j += 4) {
                    float4 t = *(const float4*)&C[(size_t)sidx[c] * NT + base + j];
                    xlv[c][j] = t.x; xlv[c][j + 1] = t.y;
                    xlv[c][j + 2] = t.z; xlv[c][j + 3] = t.w;
                }
            } else {
#pragma unroll
                for (int j = 0; j < V; j++) xlv[c][j] = 0.f;
            }
        }
        float part[EC];
#pragma unroll
        for (int c = 0; c < EC; c++) {
            float s = 0.f;
#pragma unroll
            for (int j = 0; j < V; j++) {
                float h = xlv[c][j] + xrv[j];
                float lr = h > 0.f ? h : 0.2f * h;
                s = fmaf(a[j], lr, s);
            }
            part[c] = s;
        }
#pragma unroll
        for (int off = 16; off > 0; off >>= 1) {
#pragma unroll
            for (int c = 0; c < EC; c++)
                part[c] += __shfl_xor_sync(0xffffffffu, part[c], off);
        }
        float m = emax;
#pragma unroll
        for (int c = 0; c < EC; c++)
            if (sidx[c] >= 0) m = fmaxf(m, part[c]);
        float sc = __expf(emax - m);
        denom *= sc;
#pragma unroll
        for (int j = 0; j < V; j++) acc[j] *= sc;
#pragma unroll
        for (int c = 0; c < EC; c++) {
            float w = (sidx[c] >= 0) ? __expf(part[c] - m) : 0.f;
            denom += w;
#pragma unroll
            for (int j = 0; j < V; j++) acc[j] = fmaf(w, xlv[c][j], acc[j]);
        }
        emax = m;
    }

    float inv = 1.0f / (denom + 1e-16f);
#pragma unroll
    for (int j = 0; j < V; j += 4) {
        float4 r = *(const float4*)&C[(size_t)dst * NT + 2 * F + base + j];
        float4 o;
        o.x = fmaf(acc[j + 0], inv, r.x);
        o.y = fmaf(acc[j + 1], inv, r.y);
        o.z = fmaf(acc[j + 2], inv, r.z);
        o.w = fmaf(acc[j + 3], inv, r.w);
        if (apply_elu) {
            o.x = o.x > 0.f ? o.x : expm1f(o.x);
            o.y = o.y > 0.f ? o.y : expm1f(o.y);
            o.z = o.z > 0.f ? o.z : expm1f(o.z);
            o.w = o.w > 0.f ? o.w : expm1f(o.w);
        }
        if (write_tf32) {
            o.x = __uint_as_float(f2tf32(o.x));
            o.y = __uint_as_float(f2tf32(o.y));
            o.z = __uint_as_float(f2tf32(o.z));
            o.w = __uint_as_float(f2tf32(o.w));
        }
        *(float4*)&out[(size_t)dst * F + base + j] = o;
    }
}

// ---------------- launch ----------------
extern "C" void kernel_launch(void* const* d_in, const int* in_sizes, int n_in,
                              void* d_out, int out_size)
{
    const float* x     = (const float*)d_in[0];
    const void*  ei    = d_in[1];
    const float* Wl1   = (const float*)d_in[2];
    const float* Wr1   = (const float*)d_in[3];
    const float* att1  = (const float*)d_in[4];
    const float* Wres1 = (const float*)d_in[5];
    const float* b1    = (const float*)d_in[6];
    const float* Wl2   = (const float*)d_in[7];
    const float* Wr2   = (const float*)d_in[8];
    const float* att2  = (const float*)d_in[9];
    const float* Wres2 = (const float*)d_in[10];
    const float* b2    = (const float*)d_in[11];

    float *c1, *h1, *c2, *b1p, *b2p;
    unsigned *W1p, *W2p, *xt;
    int* histp;
    cudaGetSymbolAddress((void**)&xt,  g_xt);
    cudaGetSymbolAddress((void**)&c1,  g_c1);
    cudaGetSymbolAddress((void**)&h1,  g_h1);
    cudaGetSymbolAddress((void**)&c2,  g_c2);
    cudaGetSymbolAddress((void**)&W1p, g_W1);
    cudaGetSymbolAddress((void**)&W2p, g_W2);
    cudaGetSymbolAddress((void**)&b1p, g_b1p);
    cudaGetSymbolAddress((void**)&b2p, g_b2p);
    cudaGetSymbolAddress((void**)&histp, g_hist);

    const int MB = (NN + 127) / 128;  // 391

    cudaMemsetAsync(histp, 0, NN * sizeof(int));
    // kernel order: profiler's fixed slot (4th kernel) lands on the layer-1 GEMM.
    detect_kernel<<<1, 1024>>>((const unsigned int*)ei);                          // 0
    pack_all_kernel<<<(DIN * NT1 + DH1 * NT2 + 255) / 256, 256>>>(
        Wl1, Wr1, Wres1, b1, Wl2, Wr2, Wres2, b2);                                // 1
    xconv_kernel<<<(NN * DIN / 4 + 255) / 256, 256>>>(x);                         // 2
    gemm_tf32_kernel<<<dim3(NT1 / 128, MB), 128>>>(xt, W1p, b1p, c1, NN, DIN, NT1);// 3 <- profiled
    hist_kernel<<<(NE + 255) / 256, 256>>>(ei);                                   // 4
    scan_pass1<<<SCAN_NB, 512>>>();                                               // 5
    scan_pass2<<<1, 128>>>();                                                     // 6
    scan_pass3<<<SCAN_NB, 512>>>();                                               // 7
    scatter_kernel<<<(NE + 255) / 256, 256>>>(ei);                                // 8

    edge_kernel<DH1><<<(NN * 32 + 255) / 256, 256>>>(c1, att1, h1, 1, 1);         // 9

    gemm_tf32_kernel<<<dim3(NT2 / 128, MB), 128>>>((const unsigned*)h1, W2p, b2p,
                                                   c2, NN, DH1, NT2);             // 10
    edge_kernel<DH2><<<(NN * 32 + 255) / 256, 256>>>(c2, att2, (float*)d_out, 0, 0);// 11
}

// round 12
// speedup vs baseline: 1.2117x; 1.2117x over previous
#include <cuda_runtime.h>
#include <cuda_fp16.h>
#include <math.h>
#include <stdint.h>

#define NN 50000
#define NE 640000
#define DIN 128
#define DH1 128
#define DH2 256
#define NT1 (3 * DH1)   // 384
#define NT2 (3 * DH2)   // 768

// ---------------- device scratch ----------------
__device__ __half   g_xh[NN * DIN];       // x in fp16
__device__ __half   g_xlh1[NN * DH1];     // layer1 xl (gather table, fp16)
__device__ float    g_c1[NN * 2 * DH1];   // layer1 [xr | res] fp32
__device__ __half   g_h1h[NN * DH1];      // layer1 output (fp16, feeds GEMM2)
__device__ __half   g_xlh2[NN * DH2];     // layer2 xl (gather table, fp16)
__device__ float    g_c2[NN * 2 * DH2];   // layer2 [xr | res] fp32
__device__ __half   g_W1h[NT1 * DIN];     // Wt[n][k] fp16 (k-contiguous)
__device__ __half   g_W2h[NT2 * DH1];
__device__ float    g_b1p[NT1];
__device__ float    g_b2p[NT2];
__device__ int      g_rowptr[NN + 1];
__device__ int      g_hist[NN];
__device__ int      g_cursor[NN];
__device__ int      g_srcs[NE];
__device__ int      g_is64;
#define SCAN_NB 98
__device__ int      g_bsum[SCAN_NB];
__device__ int      g_boff[SCAN_NB];

__device__ __forceinline__ void cp_async16(uint32_t dst, const void* src) {
    asm volatile("cp.async.cg.shared.global [%0], [%1], 16;" :: "r"(dst), "l"(src));
}
#define CP_COMMIT() asm volatile("cp.async.commit_group;" ::: "memory")
#define CP_WAIT0()  asm volatile("cp.async.wait_group 0;" ::: "memory")

// ---------------- edge_index dtype detection ----------------
__global__ void detect_kernel(const unsigned int* __restrict__ w) {
    __shared__ int any_nonzero;
    if (threadIdx.x == 0) any_nonzero = 0;
    __syncthreads();
    unsigned int v = w[2 * threadIdx.x + 1];
    if (v != 0u) atomicOr(&any_nonzero, 1);
    __syncthreads();
    if (threadIdx.x == 0) g_is64 = any_nonzero ? 0 : 1;
}
__device__ __forceinline__ int load_idx(const void* ei, int i) {
    return g_is64 ? (int)((const long long*)ei)[i] : ((const int*)ei)[i];
}

// ---------------- x -> fp16 ----------------
__global__ void xconv_kernel(const float* __restrict__ x) {
    int i = blockIdx.x * blockDim.x + threadIdx.x;  // float4 index
    if (i < NN * DIN / 4) {
        float4 v = ((const float4*)x)[i];
        __half2 h0 = __floats2half2_rn(v.x, v.y);
        __half2 h1 = __floats2half2_rn(v.z, v.w);
        uint2 u;
        u.x = *(unsigned*)&h0; u.y = *(unsigned*)&h1;
        ((uint2*)g_xh)[i] = u;
    }
}

// ---------------- weight packing: Wt[n][k] = fp16(W[k][n]); padded bias ----------
__global__ void pack_all_kernel(
    const float* __restrict__ Wl1, const float* __restrict__ Wr1,
    const float* __restrict__ Wres1, const float* __restrict__ b1,
    const float* __restrict__ Wl2, const float* __restrict__ Wr2,
    const float* __restrict__ Wres2, const float* __restrict__ b2)
{
    int idx = blockIdx.x * blockDim.x + threadIdx.x;
    const int S1 = NT1 * DIN;   // 49152
    const int S2 = NT2 * DH1;   // 98304
    if (idx < S1) {
        int n = idx / DIN, k = idx % DIN;
        float v = (n < DH1) ? Wl1[k * DH1 + n]
                : (n < 2 * DH1) ? Wr1[k * DH1 + (n - DH1)]
                : Wres1[k * DH1 + (n - 2 * DH1)];
        g_W1h[idx] = __float2half(v);
    } else if (idx < S1 + S2) {
        int j = idx - S1;
        int n = j / DH1, k = j % DH1;
        float v = (n < DH2) ? Wl2[k * DH2 + n]
                : (n < 2 * DH2) ? Wr2[k * DH2 + (n - DH2)]
                : Wres2[k * DH2 + (n - 2 * DH2)];
        g_W2h[j] = __float2half(v);
    }
    if (idx < NT1) g_b1p[idx] = (idx < 2 * DH1) ? 0.f : b1[idx - 2 * DH1];
    if (idx < NT2) g_b2p[idx] = (idx < 2 * DH2) ? 0.f : b2[idx - 2 * DH2];
}

// ---------------- CSR build ----------------
__global__ void hist_kernel(const void* __restrict__ ei) {
    int e = blockIdx.x * blockDim.x + threadIdx.x;
    if (e < NE) atomicAdd(&g_hist[load_idx(ei, NE + e)], 1);
}
__global__ void scan_pass1() {
    __shared__ int sh[512];
    int t = threadIdx.x;
    int i = blockIdx.x * 512 + t;
    int v = (i < NN) ? g_hist[i] : 0;
    sh[t] = v;
    __syncthreads();
    for (int off = 1; off < 512; off <<= 1) {
        int u = (t >= off) ? sh[t - off] : 0;
        __syncthreads();
        sh[t] += u;
        __syncthreads();
    }
    if (i < NN) g_rowptr[i] = sh[t] - v;
    if (t == 511) g_bsum[blockIdx.x] = sh[511];
}
__global__ void scan_pass2() {
    __shared__ int sh[128];
    int t = threadIdx.x;
    int v = (t < SCAN_NB) ? g_bsum[t] : 0;
    sh[t] = v;
    __syncthreads();
    for (int off = 1; off < 128; off <<= 1) {
        int u = (t >= off) ? sh[t - off] : 0;
        __syncthreads();
        sh[t] += u;
        __syncthreads();
    }
    if (t < SCAN_NB) g_boff[t] = sh[t] - v;
    if (t == 0) g_rowptr[NN] = NE;
}
__global__ void scan_pass3() {
    int i = blockIdx.x * 512 + threadIdx.x;
    if (i < NN) {
        int r = g_rowptr[i] + g_boff[blockIdx.x];
        g_rowptr[i] = r;
        g_cursor[i] = r;
    }
}
__global__ void scatter_kernel(const void* __restrict__ ei) {
    int e = blockIdx.x * blockDim.x + threadIdx.x;
    if (e < NE) {
        int d = load_idx(ei, NE + e);
        int p = atomicAdd(&g_cursor[d], 1);
        g_srcs[p] = load_idx(ei, e);
    }
}

// ---------------- fp16 mma.sync GEMM: full K=128 panels resident in smem ----------
// BM=128 BN=128, 128 threads, warp tile 64x64, m16n8k16. One load, one sync, no
// mainloop barriers. Row stride 136 halves (68 words) -> conflict-free frag LDS.
#define TSW 68   // words per smem row

__global__ void __launch_bounds__(128) gemm_f16_kernel(
    const __half* __restrict__ A, const __half* __restrict__ Wt,
    const float* __restrict__ bias, float* __restrict__ C,
    __half* __restrict__ XLH, int M, int F)
{
    extern __shared__ unsigned smem[];
    unsigned* As = smem;               // 128 rows x 68 words
    unsigned* Bs = smem + 128 * TSW;
    const int N2 = 2 * F;

    int tid = threadIdx.x;
    int bm = blockIdx.y * 128;
    int bn = blockIdx.x * 128;

    int warpId = tid >> 5;
    int lane = tid & 31;
    int gid = lane >> 2;      // 0..7
    int tig = lane & 3;       // 0..3
    int warp_m = warpId >> 1; // 0..1
    int warp_n = warpId & 1;  // 0..1

    float acc[4][8][4];
#pragma unroll
    for (int mt = 0; mt < 4; mt++)
#pragma unroll
        for (int nt = 0; nt < 8; nt++)
#pragma unroll
            for (int r = 0; r < 4; r++) acc[mt][nt][r] = 0.f;

    // load full panels: thread t loads A row t (256B) and B row t (256B)
    int arow = bm + tid; if (arow >= M) arow = M - 1;
    const __half* ap = A + (size_t)arow * 128;
    const __half* bp = Wt + (size_t)(bn + tid) * 128;
    uint32_t as_d = (uint32_t)__cvta_generic_to_shared(&As[tid * TSW]);
    uint32_t bs_d = (uint32_t)__cvta_generic_to_shared(&Bs[tid * TSW]);
#pragma unroll
    for (int j = 0; j < 16; j++) {
        cp_async16(as_d + j * 16, ap + j * 8);
        cp_async16(bs_d + j * 16, bp + j * 8);
    }
    CP_COMMIT();
    CP_WAIT0();
    __syncthreads();

#pragma unroll
    for (int kt = 0; kt < 8; kt++) {
        int kw = kt * 8 + tig;
        unsigned afr[4][4];
#pragma unroll
        for (int mt = 0; mt < 4; mt++) {
            int rm = warp_m * 64 + mt * 16 + gid;
            afr[mt][0] = As[(rm + 0) * TSW + kw];
            afr[mt][1] = As[(rm + 8) * TSW + kw];
            afr[mt][2] = As[(rm + 0) * TSW + kw + 4];
            afr[mt][3] = As[(rm + 8) * TSW + kw + 4];
        }
#pragma unroll
        for (int nt = 0; nt < 8; nt++) {
            int cn = warp_n * 64 + nt * 8 + gid;
            unsigned b0 = Bs[cn * TSW + kw];
            unsigned b1 = Bs[cn * TSW + kw + 4];
#pragma unroll
            for (int mt = 0; mt < 4; mt++) {
                asm volatile(
                    "mma.sync.aligned.m16n8k16.row.col.f32.f16.f16.f32 "
                    "{%0,%1,%2,%3}, {%4,%5,%6,%7}, {%8,%9}, {%0,%1,%2,%3};"
                    : "+f"(acc[mt][nt][0]), "+f"(acc[mt][nt][1]),
                      "+f"(acc[mt][nt][2]), "+f"(acc[mt][nt][3])
                    : "r"(afr[mt][0]), "r"(afr[mt][1]),
                      "r"(afr[mt][2]), "r"(afr[mt][3]),
                      "r"(b0), "r"(b1));
            }
        }
    }

    // epilogue: col<F -> xl as fp16 to XLH; else fp32 [xr|res] to C at col-F
#pragma unroll
    for (int mt = 0; mt < 4; mt++) {
        int r0 = bm + warp_m * 64 + mt * 16 + gid;
        int r1 = r0 + 8;
#pragma unroll
        for (int nt = 0; nt < 8; nt++) {
            int col = bn + warp_n * 64 + nt * 8 + tig * 2;
            if (col < F) {
                if (r0 < M) {
                    __half2 h = __floats2half2_rn(acc[mt][nt][0], acc[mt][nt][1]);
                    *(__half2*)&XLH[(size_t)r0 * F + col] = h;
                }
                if (r1 < M) {
                    __half2 h = __floats2half2_rn(acc[mt][nt][2], acc[mt][nt][3]);
                    *(__half2*)&XLH[(size_t)r1 * F + col] = h;
                }
            } else {
                float bx = bias[col], by = bias[col + 1];
                if (r0 < M) {
                    float2 o = make_float2(acc[mt][nt][0] + bx, acc[mt][nt][1] + by);
                    *(float2*)&C[(size_t)r0 * N2 + col - F] = o;
                }
                if (r1 < M) {
                    float2 o = make_float2(acc[mt][nt][2] + bx, acc[mt][nt][3] + by);
                    *(float2*)&C[(size_t)r1 * N2 + col - F] = o;
                }
            }
        }
    }
}

// ---------------- fused edge pass: fp16 gather, chunked online softmax ----------------
// xlh: [NN][F] fp16 gather table. C2: [NN][2F] fp32 = [xr | res].
template <int F>
__global__ void __launch_bounds__(256) edge_kernel(
    const __half* __restrict__ xlh, const float* __restrict__ C2,
    const float* __restrict__ att, float* __restrict__ outf,
    __half* __restrict__ outh, int apply_elu)
{
    constexpr int N2 = 2 * F;
    constexpr int V = F / 32;
    constexpr int EC = 4;
    int warp = (blockIdx.x * blockDim.x + threadIdx.x) >> 5;
    int lane = threadIdx.x & 31;
    if (warp >= NN) return;
    int dst = warp;
    const int base = lane * V;

    float a[V], xrv[V], acc[V];
#pragma unroll
    for (int j = 0; j < V; j += 4) {
        float4 t = *(const float4*)&att[base + j];
        a[j] = t.x; a[j + 1] = t.y; a[j + 2] = t.z; a[j + 3] = t.w;
        float4 r = *(const float4*)&C2[(size_t)dst * N2 + base + j];
        xrv[j] = r.x; xrv[j + 1] = r.y; xrv[j + 2] = r.z; xrv[j + 3] = r.w;
    }
#pragma unroll
    for (int j = 0; j < V; j++) acc[j] = 0.f;

    float emax = -INFINITY, denom = 0.f;
    int p0 = g_rowptr[dst], p1 = g_rowptr[dst + 1];

    for (int p = p0; p < p1; p += EC) {
        int sidx[EC];
        float xlv[EC][V];
#pragma unroll
        for (int c = 0; c < EC; c++)
            sidx[c] = (p + c < p1) ? g_srcs[p + c] : -1;
#pragma unroll
        for (int c = 0; c < EC; c++) {
            if (sidx[c] >= 0) {
                const __half* src = xlh + (size_t)sidx[c] * F + base;
                if (F == 128) {
                    uint2 u = *(const uint2*)src;
                    float2 f0 = __half22float2(*(__half2*)&u.x);
                    float2 f1 = __half22float2(*(__half2*)&u.y);
                    xlv[c][0] = f0.x; xlv[c][1] = f0.y;
                    xlv[c][2] = f1.x; xlv[c][3] = f1.y;
                } else {
                    uint4 u = *(const uint4*)src;
                    float2 f0 = __half22float2(*(__half2*)&u.x);
                    float2 f1 = __half22float2(*(__half2*)&u.y);
                    float2 f2 = __half22float2(*(__half2*)&u.z);
                    float2 f3 = __half22float2(*(__half2*)&u.w);
                    xlv[c][0] = f0.x; xlv[c][1] = f0.y;
                    xlv[c][2] = f1.x; xlv[c][3] = f1.y;
                    xlv[c][4] = f2.x; xlv[c][5] = f2.y;
                    xlv[c][6] = f3.x; xlv[c][7] = f3.y;
                }
            } else {
#pragma unroll
                for (int j = 0; j < V; j++) xlv[c][j] = 0.f;
            }
        }
        float part[EC];
#pragma unroll
        for (int c = 0; c < EC; c++) {
            float s = 0.f;
#pragma unroll
            for (int j = 0; j < V; j++) {
                float h = xlv[c][j] + xrv[j];
                float lr = h > 0.f ? h : 0.2f * h;
                s = fmaf(a[j], lr, s);
            }
            part[c] = s;
        }
#pragma unroll
        for (int off = 16; off > 0; off >>= 1) {
#pragma unroll
            for (int c = 0; c < EC; c++)
                part[c] += __shfl_xor_sync(0xffffffffu, part[c], off);
        }
        float m = emax;
#pragma unroll
        for (int c = 0; c < EC; c++)
            if (sidx[c] >= 0) m = fmaxf(m, part[c]);
        float sc = __expf(emax - m);
        denom *= sc;
#pragma unroll
        for (int j = 0; j < V; j++) acc[j] *= sc;
#pragma unroll
        for (int c = 0; c < EC; c++) {
            float w = (sidx[c] >= 0) ? __expf(part[c] - m) : 0.f;
            denom += w;
#pragma unroll
            for (int j = 0; j < V; j++) acc[j] = fmaf(w, xlv[c][j], acc[j]);
        }
        emax = m;
    }

    float inv = 1.0f / (denom + 1e-16f);
    float ov[V];
#pragma unroll
    for (int j = 0; j < V; j += 4) {
        float4 r = *(const float4*)&C2[(size_t)dst * N2 + F + base + j];
        ov[j + 0] = fmaf(acc[j + 0], inv, r.x);
        ov[j + 1] = fmaf(acc[j + 1], inv, r.y);
        ov[j + 2] = fmaf(acc[j + 2], inv, r.z);
        ov[j + 3] = fmaf(acc[j + 3], inv, r.w);
    }
    if (apply_elu) {
#pragma unroll
        for (int j = 0; j < V; j++) ov[j] = ov[j] > 0.f ? ov[j] : expm1f(ov[j]);
    }
    if (outh) {
#pragma unroll
        for (int j = 0; j < V; j += 2) {
            __half2 h = __floats2half2_rn(ov[j], ov[j + 1]);
            *(__half2*)&outh[(size_t)dst * F + base + j] = h;
        }
    } else {
#pragma unroll
        for (int j = 0; j < V; j += 4) {
            float4 o = make_float4(ov[j], ov[j + 1], ov[j + 2], ov[j + 3]);
            *(float4*)&outf[(size_t)dst * F + base + j] = o;
        }
    }
}

// ---------------- launch ----------------
extern "C" void kernel_launch(void* const* d_in, const int* in_sizes, int n_in,
                              void* d_out, int out_size)
{
    const float* x     = (const float*)d_in[0];
    const void*  ei    = d_in[1];
    const float* Wl1   = (const float*)d_in[2];
    const float* Wr1   = (const float*)d_in[3];
    const float* att1  = (const float*)d_in[4];
    const float* Wres1 = (const float*)d_in[5];
    const float* b1    = (const float*)d_in[6];
    const float* Wl2   = (const float*)d_in[7];
    const float* Wr2   = (const float*)d_in[8];
    const float* att2  = (const float*)d_in[9];
    const float* Wres2 = (const float*)d_in[10];
    const float* b2    = (const float*)d_in[11];

    __half *xh, *xlh1, *h1h, *xlh2, *W1h, *W2h;
    float *c1, *c2, *b1p, *b2p;
    int* histp;
    cudaGetSymbolAddress((void**)&xh,   g_xh);
    cudaGetSymbolAddress((void**)&xlh1, g_xlh1);
    cudaGetSymbolAddress((void**)&c1,   g_c1);
    cudaGetSymbolAddress((void**)&h1h,  g_h1h);
    cudaGetSymbolAddress((void**)&xlh2, g_xlh2);
    cudaGetSymbolAddress((void**)&c2,   g_c2);
    cudaGetSymbolAddress((void**)&W1h,  g_W1h);
    cudaGetSymbolAddress((void**)&W2h,  g_W2h);
    cudaGetSymbolAddress((void**)&b1p,  g_b1p);
    cudaGetSymbolAddress((void**)&b2p,  g_b2p);
    cudaGetSymbolAddress((void**)&histp, g_hist);

    const int GSMEM = 2 * 128 * TSW * 4;  // 69632 B
    cudaFuncSetAttribute(gemm_f16_kernel, cudaFuncAttributeMaxDynamicSharedMemorySize, GSMEM);

    const int MB = (NN + 127) / 128;  // 391

    cudaMemsetAsync(histp, 0, NN * sizeof(int));
    // kernel order: profiler's fixed slot (4th kernel) lands on the layer-1 GEMM.
    detect_kernel<<<1, 1024>>>((const unsigned int*)ei);                          // 0
    pack_all_kernel<<<(NT1 * DIN + NT2 * DH1 + 255) / 256, 256>>>(
        Wl1, Wr1, Wres1, b1, Wl2, Wr2, Wres2, b2);                                // 1
    xconv_kernel<<<(NN * DIN / 4 + 255) / 256, 256>>>(x);                         // 2
    gemm_f16_kernel<<<dim3(NT1 / 128, MB), 128, GSMEM>>>(xh, W1h, b1p, c1, xlh1,
                                                         NN, DH1);                // 3 <- profiled
    hist_kernel<<<(NE + 255) / 256, 256>>>(ei);                                   // 4
    scan_pass1<<<SCAN_NB, 512>>>();                                               // 5
    scan_pass2<<<1, 128>>>();                                                     // 6
    scan_pass3<<<SCAN_NB, 512>>>();                                               // 7
    scatter_kernel<<<(NE + 255) / 256, 256>>>(ei);                                // 8

    edge_kernel<DH1><<<(NN * 32 + 255) / 256, 256>>>(xlh1, c1, att1, nullptr,
                                                     h1h, 1);                     // 9

    gemm_f16_kernel<<<dim3(NT2 / 128, MB), 128, GSMEM>>>(h1h, W2h, b2p, c2, xlh2,
                                                         NN, DH2);                // 10
    edge_kernel<DH2><<<(NN * 32 + 255) / 256, 256>>>(xlh2, c2, att2,
                                                     (float*)d_out, nullptr, 0);  // 11
}

// round 13
// speedup vs baseline: 1.2596x; 1.0395x over previous
#include <cuda_runtime.h>
#include <cuda_fp16.h>
#include <math.h>
#include <stdint.h>

#define NN 50000
#define NE 640000
#define DIN 128
#define DH1 128
#define DH2 256
#define NT1 (3 * DH1)   // 384
#define NT2 (3 * DH2)   // 768

// ---------------- device scratch ----------------
__device__ __half   g_xh[NN * DIN];       // x in fp16
__device__ __half   g_xlh1[NN * DH1];     // layer1 xl (gather table, fp16)
__device__ float    g_c1[NN * 2 * DH1];   // layer1 [xr | res] fp32
__device__ __half   g_h1h[NN * DH1];      // layer1 output (fp16, feeds GEMM2)
__device__ __half   g_xlh2[NN * DH2];     // layer2 xl (gather table, fp16)
__device__ float    g_c2[NN * 2 * DH2];   // layer2 [xr | res] fp32
__device__ __half   g_W1h[NT1 * DIN];     // Wt[n][k] fp16 (k-contiguous)
__device__ __half   g_W2h[NT2 * DH1];
__device__ float    g_b1p[NT1];
__device__ float    g_b2p[NT2];
__device__ int      g_rowptr[NN + 1];
__device__ int      g_hist[NN];
__device__ int      g_cursor[NN];
__device__ int      g_srcs[NE];
__device__ int      g_is64;
#define SCAN_NB 98
__device__ int      g_bsum[SCAN_NB];
__device__ int      g_boff[SCAN_NB];

__device__ __forceinline__ void cp_async16(uint32_t dst, const void* src) {
    asm volatile("cp.async.cg.shared.global [%0], [%1], 16;" :: "r"(dst), "l"(src));
}
#define CP_COMMIT() asm volatile("cp.async.commit_group;" ::: "memory")
#define CP_WAIT0()  asm volatile("cp.async.wait_group 0;" ::: "memory")

// ---------------- edge_index dtype detection ----------------
__global__ void detect_kernel(const unsigned int* __restrict__ w) {
    __shared__ int any_nonzero;
    if (threadIdx.x == 0) any_nonzero = 0;
    __syncthreads();
    unsigned int v = w[2 * threadIdx.x + 1];
    if (v != 0u) atomicOr(&any_nonzero, 1);
    __syncthreads();
    if (threadIdx.x == 0) g_is64 = any_nonzero ? 0 : 1;
}
__device__ __forceinline__ int load_idx(const void* ei, int i) {
    return g_is64 ? (int)((const long long*)ei)[i] : ((const int*)ei)[i];
}

// ---------------- x -> fp16 ----------------
__global__ void xconv_kernel(const float* __restrict__ x) {
    int i = blockIdx.x * blockDim.x + threadIdx.x;  // float4 index
    if (i < NN * DIN / 4) {
        float4 v = ((const float4*)x)[i];
        __half2 h0 = __floats2half2_rn(v.x, v.y);
        __half2 h1 = __floats2half2_rn(v.z, v.w);
        uint2 u;
        u.x = *(unsigned*)&h0; u.y = *(unsigned*)&h1;
        ((uint2*)g_xh)[i] = u;
    }
}

// ---------------- weight packing: Wt[n][k] = fp16(W[k][n]); padded bias ----------
__global__ void pack_all_kernel(
    const float* __restrict__ Wl1, const float* __restrict__ Wr1,
    const float* __restrict__ Wres1, const float* __restrict__ b1,
    const float* __restrict__ Wl2, const float* __restrict__ Wr2,
    const float* __restrict__ Wres2, const float* __restrict__ b2)
{
    int idx = blockIdx.x * blockDim.x + threadIdx.x;
    const int S1 = NT1 * DIN;   // 49152
    const int S2 = NT2 * DH1;   // 98304
    if (idx < S1) {
        int n = idx / DIN, k = idx % DIN;
        float v = (n < DH1) ? Wl1[k * DH1 + n]
                : (n < 2 * DH1) ? Wr1[k * DH1 + (n - DH1)]
                : Wres1[k * DH1 + (n - 2 * DH1)];
        g_W1h[idx] = __float2half(v);
    } else if (idx < S1 + S2) {
        int j = idx - S1;
        int n = j / DH1, k = j % DH1;
        float v = (n < DH2) ? Wl2[k * DH2 + n]
                : (n < 2 * DH2) ? Wr2[k * DH2 + (n - DH2)]
                : Wres2[k * DH2 + (n - 2 * DH2)];
        g_W2h[j] = __float2half(v);
    }
    if (idx < NT1) g_b1p[idx] = (idx < 2 * DH1) ? 0.f : b1[idx - 2 * DH1];
    if (idx < NT2) g_b2p[idx] = (idx < 2 * DH2) ? 0.f : b2[idx - 2 * DH2];
}

// ---------------- CSR build ----------------
__global__ void hist_kernel(const void* __restrict__ ei) {
    int e = blockIdx.x * blockDim.x + threadIdx.x;
    if (e < NE) atomicAdd(&g_hist[load_idx(ei, NE + e)], 1);
}
__global__ void scan_pass1() {
    __shared__ int sh[512];
    int t = threadIdx.x;
    int i = blockIdx.x * 512 + t;
    int v = (i < NN) ? g_hist[i] : 0;
    sh[t] = v;
    __syncthreads();
    for (int off = 1; off < 512; off <<= 1) {
        int u = (t >= off) ? sh[t - off] : 0;
        __syncthreads();
        sh[t] += u;
        __syncthreads();
    }
    if (i < NN) g_rowptr[i] = sh[t] - v;
    if (t == 511) g_bsum[blockIdx.x] = sh[511];
}
__global__ void scan_pass2() {
    __shared__ int sh[128];
    int t = threadIdx.x;
    int v = (t < SCAN_NB) ? g_bsum[t] : 0;
    sh[t] = v;
    __syncthreads();
    for (int off = 1; off < 128; off <<= 1) {
        int u = (t >= off) ? sh[t - off] : 0;
        __syncthreads();
        sh[t] += u;
        __syncthreads();
    }
    if (t < SCAN_NB) g_boff[t] = sh[t] - v;
    if (t == 0) g_rowptr[NN] = NE;
}
__global__ void scan_pass3() {
    int i = blockIdx.x * 512 + threadIdx.x;
    if (i < NN) {
        int r = g_rowptr[i] + g_boff[blockIdx.x];
        g_rowptr[i] = r;
        g_cursor[i] = r;
    }
}
__global__ void scatter_kernel(const void* __restrict__ ei) {
    int e = blockIdx.x * blockDim.x + threadIdx.x;
    if (e < NE) {
        int d = load_idx(ei, NE + e);
        int p = atomicAdd(&g_cursor[d], 1);
        g_srcs[p] = load_idx(ei, e);
    }
}

// ---------------- fp16 mma.sync GEMM: full K=128 panels, 256 thr, warp tile 64x32 --
// One load, one sync, no mainloop barriers. Row stride 68 words -> conflict-free.
#define TSW 68   // words per smem row

__global__ void __launch_bounds__(256) gemm_f16_kernel(
    const __half* __restrict__ A, const __half* __restrict__ Wt,
    const float* __restrict__ bias, float* __restrict__ C,
    __half* __restrict__ XLH, int M, int F)
{
    extern __shared__ unsigned smem[];
    unsigned* As = smem;               // 128 rows x 68 words
    unsigned* Bs = smem + 128 * TSW;
    const int N2 = 2 * F;

    int tid = threadIdx.x;
    int bm = blockIdx.y * 128;
    int bn = blockIdx.x * 128;

    int warpId = tid >> 5;
    int lane = tid & 31;
    int gid = lane >> 2;       // 0..7
    int tig = lane & 3;        // 0..3
    int warp_m = warpId >> 2;  // 0..1 (64 rows each)
    int warp_n = warpId & 3;   // 0..3 (32 cols each)

    float acc[4][4][4];
#pragma unroll
    for (int mt = 0; mt < 4; mt++)
#pragma unroll
        for (int nt = 0; nt < 4; nt++)
#pragma unroll
            for (int r = 0; r < 4; r++) acc[mt][nt][r] = 0.f;

    // load full panels: thread t loads half of A row (t>>1) and half of B row (t>>1)
    int row = tid >> 1;
    int half = tid & 1;
    int arow = bm + row; if (arow >= M) arow = M - 1;
    const __half* ap = A + (size_t)arow * 128 + half * 64;
    const __half* bp = Wt + (size_t)(bn + row) * 128 + half * 64;
    uint32_t as_d = (uint32_t)__cvta_generic_to_shared(&As[row * TSW + half * 32]);
    uint32_t bs_d = (uint32_t)__cvta_generic_to_shared(&Bs[row * TSW + half * 32]);
#pragma unroll
    for (int j = 0; j < 8; j++) {
        cp_async16(as_d + j * 16, ap + j * 8);
        cp_async16(bs_d + j * 16, bp + j * 8);
    }
    CP_COMMIT();
    CP_WAIT0();
    __syncthreads();

#pragma unroll
    for (int kt = 0; kt < 8; kt++) {
        int kw = kt * 8 + tig;
        unsigned afr[4][4];
#pragma unroll
        for (int mt = 0; mt < 4; mt++) {
            int rm = warp_m * 64 + mt * 16 + gid;
            afr[mt][0] = As[(rm + 0) * TSW + kw];
            afr[mt][1] = As[(rm + 8) * TSW + kw];
            afr[mt][2] = As[(rm + 0) * TSW + kw + 4];
            afr[mt][3] = As[(rm + 8) * TSW + kw + 4];
        }
#pragma unroll
        for (int nt = 0; nt < 4; nt++) {
            int cn = warp_n * 32 + nt * 8 + gid;
            unsigned b0 = Bs[cn * TSW + kw];
            unsigned b1 = Bs[cn * TSW + kw + 4];
#pragma unroll
            for (int mt = 0; mt < 4; mt++) {
                asm volatile(
                    "mma.sync.aligned.m16n8k16.row.col.f32.f16.f16.f32 "
                    "{%0,%1,%2,%3}, {%4,%5,%6,%7}, {%8,%9}, {%0,%1,%2,%3};"
                    : "+f"(acc[mt][nt][0]), "+f"(acc[mt][nt][1]),
                      "+f"(acc[mt][nt][2]), "+f"(acc[mt][nt][3])
                    : "r"(afr[mt][0]), "r"(afr[mt][1]),
                      "r"(afr[mt][2]), "r"(afr[mt][3]),
                      "r"(b0), "r"(b1));
            }
        }
    }

    // epilogue: col<F -> xl as fp16 to XLH; else fp32 [xr|res] to C at col-F
#pragma unroll
    for (int mt = 0; mt < 4; mt++) {
        int r0 = bm + warp_m * 64 + mt * 16 + gid;
        int r1 = r0 + 8;
#pragma unroll
        for (int nt = 0; nt < 4; nt++) {
            int col = bn + warp_n * 32 + nt * 8 + tig * 2;
            if (col < F) {
                if (r0 < M) {
                    __half2 h = __floats2half2_rn(acc[mt][nt][0], acc[mt][nt][1]);
                    *(__half2*)&XLH[(size_t)r0 * F + col] = h;
                }
                if (r1 < M) {
                    __half2 h = __floats2half2_rn(acc[mt][nt][2], acc[mt][nt][3]);
                    *(__half2*)&XLH[(size_t)r1 * F + col] = h;
                }
            } else {
                float bx = bias[col], by = bias[col + 1];
                if (r0 < M) {
                    float2 o = make_float2(acc[mt][nt][0] + bx, acc[mt][nt][1] + by);
                    *(float2*)&C[(size_t)r0 * N2 + col - F] = o;
                }
                if (r1 < M) {
                    float2 o = make_float2(acc[mt][nt][2] + bx, acc[mt][nt][3] + by);
                    *(float2*)&C[(size_t)r1 * N2 + col - F] = o;
                }
            }
        }
    }
}

// ---------------- fused edge pass: fp16 gather, chunked online softmax ----------------
// xlh: [NN][F] fp16 gather table. C2: [NN][2F] fp32 = [xr | res].
template <int F>
__global__ void __launch_bounds__(256) edge_kernel(
    const __half* __restrict__ xlh, const float* __restrict__ C2,
    const float* __restrict__ att, float* __restrict__ outf,
    __half* __restrict__ outh, int apply_elu)
{
    constexpr int N2 = 2 * F;
    constexpr int V = F / 32;
    constexpr int EC = 4;
    int warp = (blockIdx.x * blockDim.x + threadIdx.x) >> 5;
    int lane = threadIdx.x & 31;
    if (warp >= NN) return;
    int dst = warp;
    const int base = lane * V;

    float a[V], xrv[V], acc[V];
#pragma unroll
    for (int j = 0; j < V; j += 4) {
        float4 t = *(const float4*)&att[base + j];
        a[j] = t.x; a[j + 1] = t.y; a[j + 2] = t.z; a[j + 3] = t.w;
        float4 r = *(const float4*)&C2[(size_t)dst * N2 + base + j];
        xrv[j] = r.x; xrv[j + 1] = r.y; xrv[j + 2] = r.z; xrv[j + 3] = r.w;
    }
#pragma unroll
    for (int j = 0; j < V; j++) acc[j] = 0.f;

    float emax = -INFINITY, denom = 0.f;
    int p0 = g_rowptr[dst], p1 = g_rowptr[dst + 1];

    for (int p = p0; p < p1; p += EC) {
        int sidx[EC];
        float xlv[EC][V];
#pragma unroll
        for (int c = 0; c < EC; c++)
            sidx[c] = (p + c < p1) ? g_srcs[p + c] : -1;
#pragma unroll
        for (int c = 0; c < EC; c++) {
            if (sidx[c] >= 0) {
                const __half* src = xlh + (size_t)sidx[c] * F + base;
                if (F == 128) {
                    uint2 u = *(const uint2*)src;
                    float2 f0 = __half22float2(*(__half2*)&u.x);
                    float2 f1 = __half22float2(*(__half2*)&u.y);
                    xlv[c][0] = f0.x; xlv[c][1] = f0.y;
                    xlv[c][2] = f1.x; xlv[c][3] = f1.y;
                } else {
                    uint4 u = *(const uint4*)src;
                    float2 f0 = __half22float2(*(__half2*)&u.x);
                    float2 f1 = __half22float2(*(__half2*)&u.y);
                    float2 f2 = __half22float2(*(__half2*)&u.z);
                    float2 f3 = __half22float2(*(__half2*)&u.w);
                    xlv[c][0] = f0.x; xlv[c][1] = f0.y;
                    xlv[c][2] = f1.x; xlv[c][3] = f1.y;
                    xlv[c][4] = f2.x; xlv[c][5] = f2.y;
                    xlv[c][6] = f3.x; xlv[c][7] = f3.y;
                }
            } else {
#pragma unroll
                for (int j = 0; j < V; j++) xlv[c][j] = 0.f;
            }
        }
        float part[EC];
#pragma unroll
        for (int c = 0; c < EC; c++) {
            float s = 0.f;
#pragma unroll
            for (int j = 0; j < V; j++) {
                float h = xlv[c][j] + xrv[j];
                float lr = h > 0.f ? h : 0.2f * h;
                s = fmaf(a[j], lr, s);
            }
            part[c] = s;
        }
#pragma unroll
        for (int off = 16; off > 0; off >>= 1) {
#pragma unroll
            for (int c = 0; c < EC; c++)
                part[c] += __shfl_xor_sync(0xffffffffu, part[c], off);
        }
        float m = emax;
#pragma unroll
        for (int c = 0; c < EC; c++)
            if (sidx[c] >= 0) m = fmaxf(m, part[c]);
        float sc = __expf(emax - m);
        denom *= sc;
#pragma unroll
        for (int j = 0; j < V; j++) acc[j] *= sc;
#pragma unroll
        for (int c = 0; c < EC; c++) {
            float w = (sidx[c] >= 0) ? __expf(part[c] - m) : 0.f;
            denom += w;
#pragma unroll
            for (int j = 0; j < V; j++) acc[j] = fmaf(w, xlv[c][j], acc[j]);
        }
        emax = m;
    }

    float inv = 1.0f / (denom + 1e-16f);
    float ov[V];
#pragma unroll
    for (int j = 0; j < V; j += 4) {
        float4 r = *(const float4*)&C2[(size_t)dst * N2 + F + base + j];
        ov[j + 0] = fmaf(acc[j + 0], inv, r.x);
        ov[j + 1] = fmaf(acc[j + 1], inv, r.y);
        ov[j + 2] = fmaf(acc[j + 2], inv, r.z);
        ov[j + 3] = fmaf(acc[j + 3], inv, r.w);
    }
    if (apply_elu) {
#pragma unroll
        for (int j = 0; j < V; j++) ov[j] = ov[j] > 0.f ? ov[j] : expm1f(ov[j]);
    }
    if (outh) {
#pragma unroll
        for (int j = 0; j < V; j += 2) {
            __half2 h = __floats2half2_rn(ov[j], ov[j + 1]);
            *(__half2*)&outh[(size_t)dst * F + base + j] = h;
        }
    } else {
#pragma unroll
        for (int j = 0; j < V; j += 4) {
            float4 o = make_float4(ov[j], ov[j + 1], ov[j + 2], ov[j + 3]);
            *(float4*)&outf[(size_t)dst * F + base + j] = o;
        }
    }
}

// ---------------- launch ----------------
extern "C" void kernel_launch(void* const* d_in, const int* in_sizes, int n_in,
                              void* d_out, int out_size)
{
    const float* x     = (const float*)d_in[0];
    const void*  ei    = d_in[1];
    const float* Wl1   = (const float*)d_in[2];
    const float* Wr1   = (const float*)d_in[3];
    const float* att1  = (const float*)d_in[4];
    const float* Wres1 = (const float*)d_in[5];
    const float* b1    = (const float*)d_in[6];
    const float* Wl2   = (const float*)d_in[7];
    const float* Wr2   = (const float*)d_in[8];
    const float* att2  = (const float*)d_in[9];
    const float* Wres2 = (const float*)d_in[10];
    const float* b2    = (const float*)d_in[11];

    __half *xh, *xlh1, *h1h, *xlh2, *W1h, *W2h;
    float *c1, *c2, *b1p, *b2p;
    int* histp;
    cudaGetSymbolAddress((void**)&xh,   g_xh);
    cudaGetSymbolAddress((void**)&xlh1, g_xlh1);
    cudaGetSymbolAddress((void**)&c1,   g_c1);
    cudaGetSymbolAddress((void**)&h1h,  g_h1h);
    cudaGetSymbolAddress((void**)&xlh2, g_xlh2);
    cudaGetSymbolAddress((void**)&c2,   g_c2);
    cudaGetSymbolAddress((void**)&W1h,  g_W1h);
    cudaGetSymbolAddress((void**)&W2h,  g_W2h);
    cudaGetSymbolAddress((void**)&b1p,  g_b1p);
    cudaGetSymbolAddress((void**)&b2p,  g_b2p);
    cudaGetSymbolAddress((void**)&histp, g_hist);

    const int GSMEM = 2 * 128 * TSW * 4;  // 69632 B
    cudaFuncSetAttribute(gemm_f16_kernel, cudaFuncAttributeMaxDynamicSharedMemorySize, GSMEM);

    const int MB = (NN + 127) / 128;  // 391

    cudaMemsetAsync(histp, 0, NN * sizeof(int));
    // kernel order: profiler's fixed slot (4th kernel) lands on the layer-1 GEMM.
    detect_kernel<<<1, 1024>>>((const unsigned int*)ei);                          // 0
    pack_all_kernel<<<(NT1 * DIN + NT2 * DH1 + 255) / 256, 256>>>(
        Wl1, Wr1, Wres1, b1, Wl2, Wr2, Wres2, b2);                                // 1
    xconv_kernel<<<(NN * DIN / 4 + 255) / 256, 256>>>(x);                         // 2
    gemm_f16_kernel<<<dim3(NT1 / 128, MB), 256, GSMEM>>>(xh, W1h, b1p, c1, xlh1,
                                                         NN, DH1);                // 3 <- profiled
    hist_kernel<<<(NE + 255) / 256, 256>>>(ei);                                   // 4
    scan_pass1<<<SCAN_NB, 512>>>();                                               // 5
    scan_pass2<<<1, 128>>>();                                                     // 6
    scan_pass3<<<SCAN_NB, 512>>>();                                               // 7
    scatter_kernel<<<(NE + 255) / 256, 256>>>(ei);                                // 8

    edge_kernel<DH1><<<(NN * 32 + 255) / 256, 256>>>(xlh1, c1, att1, nullptr,
                                                     h1h, 1);                     // 9

    gemm_f16_kernel<<<dim3(NT2 / 128, MB), 256, GSMEM>>>(h1h, W2h, b2p, c2, xlh2,
                                                         NN, DH2);                // 10
    edge_kernel<DH2><<<(NN * 32 + 255) / 256, 256>>>(xlh2, c2, att2,
                                                     (float*)d_out, nullptr, 0);  // 11
}

// round 14
// speedup vs baseline: 1.3090x; 1.0392x over previous
#include <cuda_runtime.h>
#include <cuda_fp16.h>
#include <math.h>
#include <stdint.h>

#define NN 50000
#define NE 640000
#define DIN 128
#define DH1 128
#define DH2 256
#define NT1 (3 * DH1)   // 384
#define NT2 (3 * DH2)   // 768

// ---------------- device scratch ----------------
__device__ __half   g_xh[NN * DIN];       // x in fp16
__device__ __half   g_xlh1[NN * DH1];     // layer1 xl (gather table, fp16)
__device__ float    g_c1[NN * 2 * DH1];   // layer1 [xr | res] fp32
__device__ __half   g_h1h[NN * DH1];      // layer1 output (fp16, feeds GEMM2)
__device__ __half   g_xlh2[NN * DH2];     // layer2 xl (gather table, fp16)
__device__ float    g_c2[NN * 2 * DH2];   // layer2 [xr | res] fp32
__device__ __half   g_W1h[NT1 * DIN];     // Wt[n][k] fp16 (k-contiguous)
__device__ __half   g_W2h[NT2 * DH1];
__device__ float    g_b1p[NT1];
__device__ float    g_b2p[NT2];
__device__ int      g_rowptr[NN + 1];
__device__ int      g_hist[NN];
__device__ int      g_cursor[NN];
__device__ int      g_srcs[NE];
__device__ int      g_is64;
#define SCAN_NB 98
__device__ int      g_bsum[SCAN_NB];
__device__ int      g_boff[SCAN_NB];

__device__ __forceinline__ void cp_async16(uint32_t dst, const void* src) {
    asm volatile("cp.async.cg.shared.global [%0], [%1], 16;" :: "r"(dst), "l"(src));
}
#define CP_COMMIT() asm volatile("cp.async.commit_group;" ::: "memory")
#define CP_WAIT0()  asm volatile("cp.async.wait_group 0;" ::: "memory")

// ---------------- edge_index dtype detection ----------------
__global__ void detect_kernel(const unsigned int* __restrict__ w) {
    __shared__ int any_nonzero;
    if (threadIdx.x == 0) any_nonzero = 0;
    __syncthreads();
    unsigned int v = w[2 * threadIdx.x + 1];
    if (v != 0u) atomicOr(&any_nonzero, 1);
    __syncthreads();
    if (threadIdx.x == 0) g_is64 = any_nonzero ? 0 : 1;
}
__device__ __forceinline__ int load_idx(const void* ei, int i) {
    return g_is64 ? (int)((const long long*)ei)[i] : ((const int*)ei)[i];
}

// ---------------- x -> fp16 ----------------
__global__ void xconv_kernel(const float* __restrict__ x) {
    int i = blockIdx.x * blockDim.x + threadIdx.x;  // float4 index
    if (i < NN * DIN / 4) {
        float4 v = ((const float4*)x)[i];
        __half2 h0 = __floats2half2_rn(v.x, v.y);
        __half2 h1 = __floats2half2_rn(v.z, v.w);
        uint2 u;
        u.x = *(unsigned*)&h0; u.y = *(unsigned*)&h1;
        ((uint2*)g_xh)[i] = u;
    }
}

// ---------------- weight packing: Wt[n][k] = fp16(W[k][n]); padded bias ----------
__global__ void pack_all_kernel(
    const float* __restrict__ Wl1, const float* __restrict__ Wr1,
    const float* __restrict__ Wres1, const float* __restrict__ b1,
    const float* __restrict__ Wl2, const float* __restrict__ Wr2,
    const float* __restrict__ Wres2, const float* __restrict__ b2)
{
    int idx = blockIdx.x * blockDim.x + threadIdx.x;
    const int S1 = NT1 * DIN;   // 49152
    const int S2 = NT2 * DH1;   // 98304
    if (idx < S1) {
        int n = idx / DIN, k = idx % DIN;
        float v = (n < DH1) ? Wl1[k * DH1 + n]
                : (n < 2 * DH1) ? Wr1[k * DH1 + (n - DH1)]
                : Wres1[k * DH1 + (n - 2 * DH1)];
        g_W1h[idx] = __float2half(v);
    } else if (idx < S1 + S2) {
        int j = idx - S1;
        int n = j / DH1, k = j % DH1;
        float v = (n < DH2) ? Wl2[k * DH2 + n]
                : (n < 2 * DH2) ? Wr2[k * DH2 + (n - DH2)]
                : Wres2[k * DH2 + (n - 2 * DH2)];
        g_W2h[j] = __float2half(v);
    }
    if (idx < NT1) g_b1p[idx] = (idx < 2 * DH1) ? 0.f : b1[idx - 2 * DH1];
    if (idx < NT2) g_b2p[idx] = (idx < 2 * DH2) ? 0.f : b2[idx - 2 * DH2];
}

// ---------------- CSR build ----------------
__global__ void hist_kernel(const void* __restrict__ ei) {
    int e = blockIdx.x * blockDim.x + threadIdx.x;
    if (e < NE) atomicAdd(&g_hist[load_idx(ei, NE + e)], 1);
}
__global__ void scan_pass1() {
    __shared__ int sh[512];
    int t = threadIdx.x;
    int i = blockIdx.x * 512 + t;
    int v = (i < NN) ? g_hist[i] : 0;
    sh[t] = v;
    __syncthreads();
    for (int off = 1; off < 512; off <<= 1) {
        int u = (t >= off) ? sh[t - off] : 0;
        __syncthreads();
        sh[t] += u;
        __syncthreads();
    }
    if (i < NN) g_rowptr[i] = sh[t] - v;
    if (t == 511) g_bsum[blockIdx.x] = sh[511];
}
__global__ void scan_pass2() {
    __shared__ int sh[128];
    int t = threadIdx.x;
    int v = (t < SCAN_NB) ? g_bsum[t] : 0;
    sh[t] = v;
    __syncthreads();
    for (int off = 1; off < 128; off <<= 1) {
        int u = (t >= off) ? sh[t - off] : 0;
        __syncthreads();
        sh[t] += u;
        __syncthreads();
    }
    if (t < SCAN_NB) g_boff[t] = sh[t] - v;
    if (t == 0) g_rowptr[NN] = NE;
}
__global__ void scan_pass3() {
    int i = blockIdx.x * 512 + threadIdx.x;
    if (i < NN) {
        int r = g_rowptr[i] + g_boff[blockIdx.x];
        g_rowptr[i] = r;
        g_cursor[i] = r;
    }
}
__global__ void scatter_kernel(const void* __restrict__ ei) {
    int e = blockIdx.x * blockDim.x + threadIdx.x;
    if (e < NE) {
        int d = load_idx(ei, NE + e);
        int p = atomicAdd(&g_cursor[d], 1);
        g_srcs[p] = load_idx(ei, e);
    }
}

// ---------------- fp16 mma.sync GEMM: full K=128 panels, 256 thr, warp tile 64x32 --
#define TSW 68   // words per smem row

__global__ void __launch_bounds__(256) gemm_f16_kernel(
    const __half* __restrict__ A, const __half* __restrict__ Wt,
    const float* __restrict__ bias, float* __restrict__ C,
    __half* __restrict__ XLH, int M, int F)
{
    extern __shared__ unsigned smem[];
    unsigned* As = smem;               // 128 rows x 68 words
    unsigned* Bs = smem + 128 * TSW;
    const int N2 = 2 * F;

    int tid = threadIdx.x;
    int bm = blockIdx.y * 128;
    int bn = blockIdx.x * 128;

    int warpId = tid >> 5;
    int lane = tid & 31;
    int gid = lane >> 2;       // 0..7
    int tig = lane & 3;        // 0..3
    int warp_m = warpId >> 2;  // 0..1 (64 rows each)
    int warp_n = warpId & 3;   // 0..3 (32 cols each)

    float acc[4][4][4];
#pragma unroll
    for (int mt = 0; mt < 4; mt++)
#pragma unroll
        for (int nt = 0; nt < 4; nt++)
#pragma unroll
            for (int r = 0; r < 4; r++) acc[mt][nt][r] = 0.f;

    // load full panels: thread t loads half of A row (t>>1) and half of B row (t>>1)
    int row = tid >> 1;
    int half = tid & 1;
    int arow = bm + row; if (arow >= M) arow = M - 1;
    const __half* ap = A + (size_t)arow * 128 + half * 64;
    const __half* bp = Wt + (size_t)(bn + row) * 128 + half * 64;
    uint32_t as_d = (uint32_t)__cvta_generic_to_shared(&As[row * TSW + half * 32]);
    uint32_t bs_d = (uint32_t)__cvta_generic_to_shared(&Bs[row * TSW + half * 32]);
#pragma unroll
    for (int j = 0; j < 8; j++) {
        cp_async16(as_d + j * 16, ap + j * 8);
        cp_async16(bs_d + j * 16, bp + j * 8);
    }
    CP_COMMIT();
    CP_WAIT0();
    __syncthreads();

#pragma unroll
    for (int kt = 0; kt < 8; kt++) {
        int kw = kt * 8 + tig;
        unsigned afr[4][4];
#pragma unroll
        for (int mt = 0; mt < 4; mt++) {
            int rm = warp_m * 64 + mt * 16 + gid;
            afr[mt][0] = As[(rm + 0) * TSW + kw];
            afr[mt][1] = As[(rm + 8) * TSW + kw];
            afr[mt][2] = As[(rm + 0) * TSW + kw + 4];
            afr[mt][3] = As[(rm + 8) * TSW + kw + 4];
        }
#pragma unroll
        for (int nt = 0; nt < 4; nt++) {
            int cn = warp_n * 32 + nt * 8 + gid;
            unsigned b0 = Bs[cn * TSW + kw];
            unsigned b1 = Bs[cn * TSW + kw + 4];
#pragma unroll
            for (int mt = 0; mt < 4; mt++) {
                asm volatile(
                    "mma.sync.aligned.m16n8k16.row.col.f32.f16.f16.f32 "
                    "{%0,%1,%2,%3}, {%4,%5,%6,%7}, {%8,%9}, {%0,%1,%2,%3};"
                    : "+f"(acc[mt][nt][0]), "+f"(acc[mt][nt][1]),
                      "+f"(acc[mt][nt][2]), "+f"(acc[mt][nt][3])
                    : "r"(afr[mt][0]), "r"(afr[mt][1]),
                      "r"(afr[mt][2]), "r"(afr[mt][3]),
                      "r"(b0), "r"(b1));
            }
        }
    }

    // epilogue: col<F -> xl as fp16 to XLH; else fp32 [xr|res] to C at col-F
#pragma unroll
    for (int mt = 0; mt < 4; mt++) {
        int r0 = bm + warp_m * 64 + mt * 16 + gid;
        int r1 = r0 + 8;
#pragma unroll
        for (int nt = 0; nt < 4; nt++) {
            int col = bn + warp_n * 32 + nt * 8 + tig * 2;
            if (col < F) {
                if (r0 < M) {
                    __half2 h = __floats2half2_rn(acc[mt][nt][0], acc[mt][nt][1]);
                    *(__half2*)&XLH[(size_t)r0 * F + col] = h;
                }
                if (r1 < M) {
                    __half2 h = __floats2half2_rn(acc[mt][nt][2], acc[mt][nt][3]);
                    *(__half2*)&XLH[(size_t)r1 * F + col] = h;
                }
            } else {
                float bx = bias[col], by = bias[col + 1];
                if (r0 < M) {
                    float2 o = make_float2(acc[mt][nt][0] + bx, acc[mt][nt][1] + by);
                    *(float2*)&C[(size_t)r0 * N2 + col - F] = o;
                }
                if (r1 < M) {
                    float2 o = make_float2(acc[mt][nt][2] + bx, acc[mt][nt][3] + by);
                    *(float2*)&C[(size_t)r1 * N2 + col - F] = o;
                }
            }
        }
    }
}

// ---------------- fused edge pass: fp16 gather, chunked online softmax ----------------
template <int F>
__global__ void __launch_bounds__(256) edge_kernel(
    const __half* __restrict__ xlh, const float* __restrict__ C2,
    const float* __restrict__ att, float* __restrict__ outf,
    __half* __restrict__ outh, int apply_elu)
{
    constexpr int N2 = 2 * F;
    constexpr int V = F / 32;
    constexpr int EC = 4;
    int warp = (blockIdx.x * blockDim.x + threadIdx.x) >> 5;
    int lane = threadIdx.x & 31;
    if (warp >= NN) return;
    int dst = warp;
    const int base = lane * V;

    float a[V], xrv[V], acc[V];
#pragma unroll
    for (int j = 0; j < V; j += 4) {
        float4 t = *(const float4*)&att[base + j];
        a[j] = t.x; a[j + 1] = t.y; a[j + 2] = t.z; a[j + 3] = t.w;
        float4 r = *(const float4*)&C2[(size_t)dst * N2 + base + j];
        xrv[j] = r.x; xrv[j + 1] = r.y; xrv[j + 2] = r.z; xrv[j + 3] = r.w;
    }
#pragma unroll
    for (int j = 0; j < V; j++) acc[j] = 0.f;

    float emax = -INFINITY, denom = 0.f;
    int p0 = g_rowptr[dst], p1 = g_rowptr[dst + 1];

    for (int p = p0; p < p1; p += EC) {
        int sidx[EC];
        float xlv[EC][V];
#pragma unroll
        for (int c = 0; c < EC; c++)
            sidx[c] = (p + c < p1) ? g_srcs[p + c] : -1;
#pragma unroll
        for (int c = 0; c < EC; c++) {
            if (sidx[c] >= 0) {
                const __half* src = xlh + (size_t)sidx[c] * F + base;
                if (F == 128) {
                    uint2 u = *(const uint2*)src;
                    float2 f0 = __half22float2(*(__half2*)&u.x);
                    float2 f1 = __half22float2(*(__half2*)&u.y);
                    xlv[c][0] = f0.x; xlv[c][1] = f0.y;
                    xlv[c][2] = f1.x; xlv[c][3] = f1.y;
                } else {
                    uint4 u = *(const uint4*)src;
                    float2 f0 = __half22float2(*(__half2*)&u.x);
                    float2 f1 = __half22float2(*(__half2*)&u.y);
                    float2 f2 = __half22float2(*(__half2*)&u.z);
                    float2 f3 = __half22float2(*(__half2*)&u.w);
                    xlv[c][0] = f0.x; xlv[c][1] = f0.y;
                    xlv[c][2] = f1.x; xlv[c][3] = f1.y;
                    xlv[c][4] = f2.x; xlv[c][5] = f2.y;
                    xlv[c][6] = f3.x; xlv[c][7] = f3.y;
                }
            } else {
#pragma unroll
                for (int j = 0; j < V; j++) xlv[c][j] = 0.f;
            }
        }
        float part[EC];
#pragma unroll
        for (int c = 0; c < EC; c++) {
            float s = 0.f;
#pragma unroll
            for (int j = 0; j < V; j++) {
                float h = xlv[c][j] + xrv[j];
                float lr = h > 0.f ? h : 0.2f * h;
                s = fmaf(a[j], lr, s);
            }
            part[c] = s;
        }
#pragma unroll
        for (int off = 16; off > 0; off >>= 1) {
#pragma unroll
            for (int c = 0; c < EC; c++)
                part[c] += __shfl_xor_sync(0xffffffffu, part[c], off);
        }
        float m = emax;
#pragma unroll
        for (int c = 0; c < EC; c++)
            if (sidx[c] >= 0) m = fmaxf(m, part[c]);
        float sc = __expf(emax - m);
        denom *= sc;
#pragma unroll
        for (int j = 0; j < V; j++) acc[j] *= sc;
#pragma unroll
        for (int c = 0; c < EC; c++) {
            float w = (sidx[c] >= 0) ? __expf(part[c] - m) : 0.f;
            denom += w;
#pragma unroll
            for (int j = 0; j < V; j++) acc[j] = fmaf(w, xlv[c][j], acc[j]);
        }
        emax = m;
    }

    float inv = 1.0f / (denom + 1e-16f);
    float ov[V];
#pragma unroll
    for (int j = 0; j < V; j += 4) {
        float4 r = *(const float4*)&C2[(size_t)dst * N2 + F + base + j];
        ov[j + 0] = fmaf(acc[j + 0], inv, r.x);
        ov[j + 1] = fmaf(acc[j + 1], inv, r.y);
        ov[j + 2] = fmaf(acc[j + 2], inv, r.z);
        ov[j + 3] = fmaf(acc[j + 3], inv, r.w);
    }
    if (apply_elu) {
#pragma unroll
        for (int j = 0; j < V; j++) ov[j] = ov[j] > 0.f ? ov[j] : expm1f(ov[j]);
    }
    if (outh) {
#pragma unroll
        for (int j = 0; j < V; j += 2) {
            __half2 h = __floats2half2_rn(ov[j], ov[j + 1]);
            *(__half2*)&outh[(size_t)dst * F + base + j] = h;
        }
    } else {
#pragma unroll
        for (int j = 0; j < V; j += 4) {
            float4 o = make_float4(ov[j], ov[j + 1], ov[j + 2], ov[j + 3]);
            *(float4*)&outf[(size_t)dst * F + base + j] = o;
        }
    }
}

// ---------------- launch: fork-join two-stream graph ----------------
extern "C" void kernel_launch(void* const* d_in, const int* in_sizes, int n_in,
                              void* d_out, int out_size)
{
    const float* x     = (const float*)d_in[0];
    const void*  ei    = d_in[1];
    const float* Wl1   = (const float*)d_in[2];
    const float* Wr1   = (const float*)d_in[3];
    const float* att1  = (const float*)d_in[4];
    const float* Wres1 = (const float*)d_in[5];
    const float* b1    = (const float*)d_in[6];
    const float* Wl2   = (const float*)d_in[7];
    const float* Wr2   = (const float*)d_in[8];
    const float* att2  = (const float*)d_in[9];
    const float* Wres2 = (const float*)d_in[10];
    const float* b2    = (const float*)d_in[11];

    __half *xh, *xlh1, *h1h, *xlh2, *W1h, *W2h;
    float *c1, *c2, *b1p, *b2p;
    int* histp;
    cudaGetSymbolAddress((void**)&xh,   g_xh);
    cudaGetSymbolAddress((void**)&xlh1, g_xlh1);
    cudaGetSymbolAddress((void**)&c1,   g_c1);
    cudaGetSymbolAddress((void**)&h1h,  g_h1h);
    cudaGetSymbolAddress((void**)&xlh2, g_xlh2);
    cudaGetSymbolAddress((void**)&c2,   g_c2);
    cudaGetSymbolAddress((void**)&W1h,  g_W1h);
    cudaGetSymbolAddress((void**)&W2h,  g_W2h);
    cudaGetSymbolAddress((void**)&b1p,  g_b1p);
    cudaGetSymbolAddress((void**)&b2p,  g_b2p);
    cudaGetSymbolAddress((void**)&histp, g_hist);

    const int GSMEM = 2 * 128 * TSW * 4;  // 69632 B
    cudaFuncSetAttribute(gemm_f16_kernel, cudaFuncAttributeMaxDynamicSharedMemorySize, GSMEM);

    const int MB = (NN + 127) / 128;  // 391

    // one-time resources (host-side only; no device allocation)
    static cudaStream_t s2 = nullptr;
    static cudaEvent_t evFork = nullptr, evJoin = nullptr;
    if (!s2) {
        cudaStreamCreateWithFlags(&s2, cudaStreamNonBlocking);
        cudaEventCreateWithFlags(&evFork, cudaEventDisableTiming);
        cudaEventCreateWithFlags(&evJoin, cudaEventDisableTiming);
    }

    // fork: CSR branch on s2, compute branch on origin (NULL) stream
    cudaEventRecord(evFork, 0);
    cudaStreamWaitEvent(s2, evFork, 0);

    // --- CSR branch (s2): detect -> memset -> hist -> scan -> scatter ---
    detect_kernel<<<1, 1024, 0, s2>>>((const unsigned int*)ei);
    cudaMemsetAsync(histp, 0, NN * sizeof(int), s2);
    hist_kernel<<<(NE + 255) / 256, 256, 0, s2>>>(ei);
    scan_pass1<<<SCAN_NB, 512, 0, s2>>>();
    scan_pass2<<<1, 128, 0, s2>>>();
    scan_pass3<<<SCAN_NB, 512, 0, s2>>>();
    scatter_kernel<<<(NE + 255) / 256, 256, 0, s2>>>(ei);
    cudaEventRecord(evJoin, s2);

    // --- compute branch (origin): conversions + layer-1 GEMM ---
    pack_all_kernel<<<(NT1 * DIN + NT2 * DH1 + 255) / 256, 256>>>(
        Wl1, Wr1, Wres1, b1, Wl2, Wr2, Wres2, b2);
    xconv_kernel<<<(NN * DIN / 4 + 255) / 256, 256>>>(x);
    gemm_f16_kernel<<<dim3(NT1 / 128, MB), 256, GSMEM>>>(xh, W1h, b1p, c1, xlh1,
                                                         NN, DH1);

    // join: edge1 needs CSR + GEMM1
    cudaStreamWaitEvent(0, evJoin, 0);

    edge_kernel<DH1><<<(NN * 32 + 255) / 256, 256>>>(xlh1, c1, att1, nullptr,
                                                     h1h, 1);
    gemm_f16_kernel<<<dim3(NT2 / 128, MB), 256, GSMEM>>>(h1h, W2h, b2p, c2, xlh2,
                                                         NN, DH2);
    edge_kernel<DH2><<<(NN * 32 + 255) / 256, 256>>>(xlh2, c2, att2,
                                                     (float*)d_out, nullptr, 0);
}